// round 1
// baseline (speedup 1.0000x reference)
#include <cuda_runtime.h>
#include <math.h>

#define NG 978
#define HD 300
#define NB 128
#define H2 512

// ---------------- scratch (no allocs allowed) ----------------
__device__ float d_deg[NG];
__device__ float d_dinv[NG];
__device__ float d_bufA[NG * HD];
__device__ float d_bufB[NG * HD];
__device__ float d_hg[NG * H2];
__device__ float d_hm[NB * H2];
__device__ float d_pool[NB * H2];

// ---------------- small helper kernels ----------------
__global__ void k_deg_init() {
    int i = blockIdx.x * blockDim.x + threadIdx.x;
    if (i < NG) d_deg[i] = 1.0f;  // self-loop
}

__global__ void k_deg_count(const int* __restrict__ dst, int E) {
    int i = blockIdx.x * blockDim.x + threadIdx.x;
    if (i < E) atomicAdd(&d_deg[dst[i]], 1.0f);
}

__global__ void k_dinv() {
    int i = blockIdx.x * blockDim.x + threadIdx.x;
    if (i < NG) d_dinv[i] = rsqrtf(d_deg[i]);
}

// out[n][f] = bias[f] + in[n][f] * dinv[n]^2   (self-loop term + bias init)
__global__ void k_scatter_init(const float* __restrict__ in, float* __restrict__ outp,
                               const float* __restrict__ bias) {
    int idx = blockIdx.x * blockDim.x + threadIdx.x;
    if (idx >= NG * HD) return;
    int n = idx / HD;
    int f = idx - n * HD;
    float di = d_dinv[n];
    outp[idx] = bias[f] + in[idx] * di * di;
}

// out[dst][f] += in[src][f] * dinv[src]*dinv[dst]
__global__ void k_scatter_edges(const float* __restrict__ in, float* __restrict__ outp,
                                const int* __restrict__ src, const int* __restrict__ dst,
                                int E) {
    int idx = blockIdx.x * blockDim.x + threadIdx.x;
    if (idx >= E * HD) return;
    int e = idx / HD;
    int f = idx - e * HD;
    int s = src[e], d = dst[e];
    atomicAdd(&outp[d * HD + f], in[s * HD + f] * d_dinv[s] * d_dinv[d]);
}

__global__ void k_zero(float* p, int n) {
    int i = blockIdx.x * blockDim.x + threadIdx.x;
    if (i < n) p[i] = 0.0f;
}

// ---------------- generic small SGEMM ----------------
// C[m][n] = alpha * sum_k A[m][k] * B[k][n] + (bias ? bias[n] : 0)
// A row-major [M,lda], B row-major [K,ldb], C row-major [M,ldc]
__global__ void __launch_bounds__(256) sgemm(
    const float* __restrict__ A, int lda,
    const float* __restrict__ B, int ldb,
    float* __restrict__ C, int ldc,
    int M, int N, int K,
    const float* __restrict__ bias, float alpha) {
    __shared__ float As[16][65];
    __shared__ float Bs[16][64];
    int tid = threadIdx.x;
    int n0 = blockIdx.x * 64;
    int m0 = blockIdx.y * 64;
    int row0 = (tid >> 4) << 2;   // 0..60
    int col0 = (tid & 15) << 2;   // 0..60
    float acc[4][4];
#pragma unroll
    for (int r = 0; r < 4; r++)
#pragma unroll
        for (int c = 0; c < 4; c++) acc[r][c] = 0.0f;

    for (int k0 = 0; k0 < K; k0 += 16) {
#pragma unroll
        for (int i = 0; i < 4; i++) {
            int e = tid + i * 256;
            int kk = e & 15;
            int r = e >> 4;
            int gm = m0 + r, gk = k0 + kk;
            As[kk][r] = (gm < M && gk < K) ? A[gm * lda + gk] : 0.0f;
        }
#pragma unroll
        for (int i = 0; i < 4; i++) {
            int e = tid + i * 256;
            int c = e & 63;
            int kk = e >> 6;
            int gn = n0 + c, gk = k0 + kk;
            Bs[kk][c] = (gn < N && gk < K) ? B[gk * ldb + gn] : 0.0f;
        }
        __syncthreads();
#pragma unroll
        for (int k = 0; k < 16; k++) {
            float a[4];
#pragma unroll
            for (int r = 0; r < 4; r++) a[r] = As[k][row0 + r];
            float4 bv = *(const float4*)&Bs[k][col0];
#pragma unroll
            for (int r = 0; r < 4; r++) {
                acc[r][0] = fmaf(a[r], bv.x, acc[r][0]);
                acc[r][1] = fmaf(a[r], bv.y, acc[r][1]);
                acc[r][2] = fmaf(a[r], bv.z, acc[r][2]);
                acc[r][3] = fmaf(a[r], bv.w, acc[r][3]);
            }
        }
        __syncthreads();
    }
#pragma unroll
    for (int r = 0; r < 4; r++) {
        int gm = m0 + row0 + r;
        if (gm >= M) continue;
#pragma unroll
        for (int c = 0; c < 4; c++) {
            int gn = n0 + col0 + c;
            if (gn >= N) continue;
            float v = alpha * acc[r][c];
            if (bias) v += bias[gn];
            C[gm * ldc + gn] = v;
        }
    }
}

// ---------------- fused FFN (the hot kernel, 131 GFLOP) ----------------
// One block = (64 genes, 1 batch). X tile lives in SMEM; two 512x512 GEMM
// layers with ReLU fused; gene-mean accumulated into d_pool via atomics.
__global__ void __launch_bounds__(256, 1) k_ffn_fused(
    const float* __restrict__ hg, const float* __restrict__ hm,
    const float* __restrict__ b1,
    const float* __restrict__ W2, const float* __restrict__ b2,
    const float* __restrict__ W3, const float* __restrict__ b3,
    float* __restrict__ pool) {
    extern __shared__ float smem[];
    float* X = smem;            // [64][512]
    float* Wc = smem + 64 * 512;  // [16][512]
    const int tid = threadIdx.x;
    const int b = blockIdx.y;
    const int g0 = blockIdx.x * 64;
    const int nvalid = min(64, NG - g0);

    // phase 0: X = relu(hg[g] + hm[b] + b1)
    for (int idx = tid; idx < 64 * 512; idx += 256) {
        int i = idx >> 9, k = idx & 511;
        float v = 0.0f;
        if (i < nvalid) v = fmaxf(hg[(g0 + i) * 512 + k] + hm[b * 512 + k] + b1[k], 0.0f);
        X[idx] = v;
    }

    const int lane = tid & 31;
    const int wrow = (tid >> 5) * 8;  // 8 warps x 8 rows
    const int c0 = lane * 4;          // cols: c0 + gq*128
    float acc[8][16];

    for (int layer = 0; layer < 2; ++layer) {
        const float* W = layer ? W3 : W2;
        const float* bias = layer ? b3 : b2;
#pragma unroll
        for (int r = 0; r < 8; r++)
#pragma unroll
            for (int c = 0; c < 16; c++) acc[r][c] = 0.0f;

        for (int kc = 0; kc < 512; kc += 16) {
            __syncthreads();  // Wc reuse + (first iter) X visibility
#pragma unroll
            for (int l = 0; l < 8; ++l) {
                int idx4 = tid + l * 256;  // < 2048 float4s = 16*512 floats
                ((float4*)Wc)[idx4] = ((const float4*)(W + kc * 512))[idx4];
            }
            __syncthreads();
#pragma unroll 4
            for (int k = 0; k < 16; ++k) {
                float a[8];
#pragma unroll
                for (int r = 0; r < 8; r++) a[r] = X[(wrow + r) * 512 + kc + k];
#pragma unroll
                for (int gq = 0; gq < 4; ++gq) {
                    float4 bv = *(const float4*)&Wc[k * 512 + c0 + gq * 128];
#pragma unroll
                    for (int r = 0; r < 8; r++) {
                        acc[r][gq * 4 + 0] = fmaf(a[r], bv.x, acc[r][gq * 4 + 0]);
                        acc[r][gq * 4 + 1] = fmaf(a[r], bv.y, acc[r][gq * 4 + 1]);
                        acc[r][gq * 4 + 2] = fmaf(a[r], bv.z, acc[r][gq * 4 + 2]);
                        acc[r][gq * 4 + 3] = fmaf(a[r], bv.w, acc[r][gq * 4 + 3]);
                    }
                }
            }
        }
        __syncthreads();  // all X reads done before epilogue writes

        if (layer == 0) {
            // X <- relu(acc + b2)  (becomes input to layer 2)
#pragma unroll
            for (int gq = 0; gq < 4; ++gq) {
                int col = c0 + gq * 128;
                float4 bb = *(const float4*)&bias[col];
#pragma unroll
                for (int r = 0; r < 8; r++) {
                    float4 v;
                    v.x = fmaxf(acc[r][gq * 4 + 0] + bb.x, 0.0f);
                    v.y = fmaxf(acc[r][gq * 4 + 1] + bb.y, 0.0f);
                    v.z = fmaxf(acc[r][gq * 4 + 2] + bb.z, 0.0f);
                    v.w = fmaxf(acc[r][gq * 4 + 3] + bb.w, 0.0f);
                    *(float4*)&X[(wrow + r) * 512 + col] = v;
                }
            }
        } else {
            // gene-mean partial: reduce relu(acc + b3) over valid rows into pool[b]
            float* red = X;  // reuse SMEM
            for (int i2 = tid; i2 < 512; i2 += 256) red[i2] = 0.0f;
            __syncthreads();
#pragma unroll
            for (int gq = 0; gq < 4; ++gq) {
                int col = c0 + gq * 128;
                float4 bb = *(const float4*)&bias[col];
                float s0 = 0.f, s1 = 0.f, s2 = 0.f, s3 = 0.f;
#pragma unroll
                for (int r = 0; r < 8; r++) {
                    if (wrow + r < nvalid) {
                        s0 += fmaxf(acc[r][gq * 4 + 0] + bb.x, 0.0f);
                        s1 += fmaxf(acc[r][gq * 4 + 1] + bb.y, 0.0f);
                        s2 += fmaxf(acc[r][gq * 4 + 2] + bb.z, 0.0f);
                        s3 += fmaxf(acc[r][gq * 4 + 3] + bb.w, 0.0f);
                    }
                }
                atomicAdd(&red[col + 0], s0);
                atomicAdd(&red[col + 1], s1);
                atomicAdd(&red[col + 2], s2);
                atomicAdd(&red[col + 3], s3);
            }
            __syncthreads();
            for (int i2 = tid; i2 < 512; i2 += 256)
                atomicAdd(&pool[b * 512 + i2], red[i2]);
        }
    }
}

// ---------------- launch ----------------
extern "C" void kernel_launch(void* const* d_in, const int* in_sizes, int n_in,
                              void* d_out, int out_size) {
    const float* mol  = (const float*)d_in[0];
    const float* gene = (const float*)d_in[1];
    const int*   ei   = (const int*)d_in[2];
    const float* g1w  = (const float*)d_in[3];
    const float* g1b  = (const float*)d_in[4];
    const float* g2w  = (const float*)d_in[5];
    const float* g2b  = (const float*)d_in[6];
    const float* f1w  = (const float*)d_in[7];
    const float* f1b  = (const float*)d_in[8];
    const float* f2w  = (const float*)d_in[9];
    const float* f2b  = (const float*)d_in[10];
    const float* f3w  = (const float*)d_in[11];
    const float* f3b  = (const float*)d_in[12];
    const float* f4w  = (const float*)d_in[13];
    const float* f4b  = (const float*)d_in[14];
    float* out = (float*)d_out;

    int E = in_sizes[2] / 2;
    const int* src = ei;
    const int* dst = ei + E;

    float *bufA, *bufB, *hg, *hm, *pool;
    cudaGetSymbolAddress((void**)&bufA, d_bufA);
    cudaGetSymbolAddress((void**)&bufB, d_bufB);
    cudaGetSymbolAddress((void**)&hg, d_hg);
    cudaGetSymbolAddress((void**)&hm, d_hm);
    cudaGetSymbolAddress((void**)&pool, d_pool);

    // degree + normalization
    k_deg_init<<<(NG + 255) / 256, 256>>>();
    k_deg_count<<<(E + 255) / 256, 256>>>(dst, E);
    k_dinv<<<(NG + 255) / 256, 256>>>();

    // GCN layer 1
    sgemm<<<dim3((HD + 63) / 64, (NG + 63) / 64), 256>>>(
        gene, HD, g1w, HD, bufA, HD, NG, HD, HD, nullptr, 1.0f);
    k_scatter_init<<<(NG * HD + 255) / 256, 256>>>(bufA, bufB, g1b);
    k_scatter_edges<<<(E * HD + 255) / 256, 256>>>(bufA, bufB, src, dst, E);

    // GCN layer 2
    sgemm<<<dim3((HD + 63) / 64, (NG + 63) / 64), 256>>>(
        bufB, HD, g2w, HD, bufA, HD, NG, HD, HD, nullptr, 1.0f);
    k_scatter_init<<<(NG * HD + 255) / 256, 256>>>(bufA, bufB, g2b);
    k_scatter_edges<<<(E * HD + 255) / 256, 256>>>(bufA, bufB, src, dst, E);

    // ffn1 split: hg = g2 @ W1[:300], hm = mol @ W1[300:]
    sgemm<<<dim3(8, (NG + 63) / 64), 256>>>(
        bufB, HD, f1w, H2, hg, H2, NG, H2, HD, nullptr, 1.0f);
    sgemm<<<dim3(8, 2), 256>>>(
        mol, HD, f1w + HD * H2, H2, hm, H2, NB, H2, HD, nullptr, 1.0f);

    // pool accumulator
    k_zero<<<(NB * H2 + 255) / 256, 256>>>(pool, NB * H2);

    // fused ffn2+ffn3+mean-partial
    int smem_bytes = (64 * 512 + 16 * 512) * sizeof(float);  // 163840
    cudaFuncSetAttribute(k_ffn_fused, cudaFuncAttributeMaxDynamicSharedMemorySize, smem_bytes);
    k_ffn_fused<<<dim3(16, NB), 256, smem_bytes>>>(hg, hm, f1b, f2w, f2b, f3w, f3b, pool);

    // out = (pool/978) @ ffn4_w + ffn4_b
    sgemm<<<dim3((NG + 63) / 64, 2), 256>>>(
        pool, H2, f4w, NG, out, NG, NB, NG, H2, f4b, 1.0f / 978.0f);
}

// round 4
// speedup vs baseline: 2.8676x; 2.8676x over previous
#include <cuda_runtime.h>
#include <math.h>
#include <stdint.h>

#define NG 978
#define HD 300
#define NB 128
#define H2 512

// ---------------- scratch (no allocs allowed) ----------------
__device__ float d_deg[NG];
__device__ float d_dinv[NG];
__device__ float d_bufA[NG * HD];
__device__ float d_bufB[NG * HD];
__device__ float d_hg[NG * H2];
__device__ float d_hm[NB * H2];
__device__ float d_pool[NB * H2];
__device__ float d_w2r[H2 * H2];   // tf32-rounded W2, [k][n]
__device__ float d_w3r[H2 * H2];   // tf32-rounded W3, [k][n]

// ---------------- helpers ----------------
__device__ __forceinline__ float cvt_tf32(float x) {
    uint32_t o;
    asm("cvt.rna.tf32.f32 %0, %1;" : "=r"(o) : "f"(x));
    return __uint_as_float(o);
}
__device__ __forceinline__ uint32_t smem_u32(const void* p) {
    uint32_t a;
    asm("{ .reg .u64 t; cvta.to.shared.u64 t, %1; cvt.u32.u64 %0, t; }" : "=r"(a) : "l"(p));
    return a;
}
__device__ __forceinline__ void cp_async16(uint32_t saddr, const void* gptr) {
    asm volatile("cp.async.cg.shared.global [%0], [%1], 16;" :: "r"(saddr), "l"(gptr));
}
__device__ __forceinline__ void cp_commit() {
    asm volatile("cp.async.commit_group;");
}
template <int N>
__device__ __forceinline__ void cp_wait() {
    asm volatile("cp.async.wait_group %0;" :: "n"(N));
}
__device__ __forceinline__ void mma_tf32(float* c, const uint32_t* a, uint32_t b0, uint32_t b1) {
    asm volatile(
        "mma.sync.aligned.m16n8k8.row.col.f32.tf32.tf32.f32 "
        "{%0,%1,%2,%3}, {%4,%5,%6,%7}, {%8,%9}, {%0,%1,%2,%3};"
        : "+f"(c[0]), "+f"(c[1]), "+f"(c[2]), "+f"(c[3])
        : "r"(a[0]), "r"(a[1]), "r"(a[2]), "r"(a[3]), "r"(b0), "r"(b1));
}

// ---------------- small helper kernels ----------------
__global__ void k_deg_init() {
    int i = blockIdx.x * blockDim.x + threadIdx.x;
    if (i < NG) d_deg[i] = 1.0f;
}
__global__ void k_deg_count(const int* __restrict__ dst, int E) {
    int i = blockIdx.x * blockDim.x + threadIdx.x;
    if (i < E) atomicAdd(&d_deg[dst[i]], 1.0f);
}
__global__ void k_dinv() {
    int i = blockIdx.x * blockDim.x + threadIdx.x;
    if (i < NG) d_dinv[i] = rsqrtf(d_deg[i]);
}
__global__ void k_scatter_init(const float* __restrict__ in, float* __restrict__ outp,
                               const float* __restrict__ bias) {
    int idx = blockIdx.x * blockDim.x + threadIdx.x;
    if (idx >= NG * HD) return;
    int n = idx / HD;
    int f = idx - n * HD;
    float di = d_dinv[n];
    outp[idx] = bias[f] + in[idx] * di * di;
}
__global__ void k_scatter_edges(const float* __restrict__ in, float* __restrict__ outp,
                                const int* __restrict__ src, const int* __restrict__ dst,
                                int E) {
    int idx = blockIdx.x * blockDim.x + threadIdx.x;
    if (idx >= E * HD) return;
    int e = idx / HD;
    int f = idx - e * HD;
    int s = src[e], d = dst[e];
    atomicAdd(&outp[d * HD + f], in[s * HD + f] * d_dinv[s] * d_dinv[d]);
}
__global__ void k_zero(float* p, int n) {
    int i = blockIdx.x * blockDim.x + threadIdx.x;
    if (i < n) p[i] = 0.0f;
}
__global__ void k_round_tf32(const float* __restrict__ W, float* __restrict__ O, int n) {
    int i = blockIdx.x * blockDim.x + threadIdx.x;
    if (i < n) O[i] = cvt_tf32(W[i]);
}

// ---------------- generic small SGEMM (GCN / ffn1 / ffn4) ----------------
__global__ void __launch_bounds__(256) sgemm(
    const float* __restrict__ A, int lda,
    const float* __restrict__ B, int ldb,
    float* __restrict__ C, int ldc,
    int M, int N, int K,
    const float* __restrict__ bias, float alpha) {
    __shared__ float As[16][65];
    __shared__ float Bs[16][64];
    int tid = threadIdx.x;
    int n0 = blockIdx.x * 64;
    int m0 = blockIdx.y * 64;
    int row0 = (tid >> 4) << 2;
    int col0 = (tid & 15) << 2;
    float acc[4][4];
#pragma unroll
    for (int r = 0; r < 4; r++)
#pragma unroll
        for (int c = 0; c < 4; c++) acc[r][c] = 0.0f;

    for (int k0 = 0; k0 < K; k0 += 16) {
#pragma unroll
        for (int i = 0; i < 4; i++) {
            int e = tid + i * 256;
            int kk = e & 15;
            int r = e >> 4;
            int gm = m0 + r, gk = k0 + kk;
            As[kk][r] = (gm < M && gk < K) ? A[gm * lda + gk] : 0.0f;
        }
#pragma unroll
        for (int i = 0; i < 4; i++) {
            int e = tid + i * 256;
            int c = e & 63;
            int kk = e >> 6;
            int gn = n0 + c, gk = k0 + kk;
            Bs[kk][c] = (gn < N && gk < K) ? B[gk * ldb + gn] : 0.0f;
        }
        __syncthreads();
#pragma unroll
        for (int k = 0; k < 16; k++) {
            float a[4];
#pragma unroll
            for (int r = 0; r < 4; r++) a[r] = As[k][row0 + r];
            float4 bv = *(const float4*)&Bs[k][col0];
#pragma unroll
            for (int r = 0; r < 4; r++) {
                acc[r][0] = fmaf(a[r], bv.x, acc[r][0]);
                acc[r][1] = fmaf(a[r], bv.y, acc[r][1]);
                acc[r][2] = fmaf(a[r], bv.z, acc[r][2]);
                acc[r][3] = fmaf(a[r], bv.w, acc[r][3]);
            }
        }
        __syncthreads();
    }
#pragma unroll
    for (int r = 0; r < 4; r++) {
        int gm = m0 + row0 + r;
        if (gm >= M) continue;
#pragma unroll
        for (int c = 0; c < 4; c++) {
            int gn = n0 + col0 + c;
            if (gn >= N) continue;
            float v = alpha * acc[r][c];
            if (bias) v += bias[gn];
            C[gm * ldc + gn] = v;
        }
    }
}

// ---------------- fused FFN via mma.sync tf32 ----------------
// Block = (64 genes, 1 batch), 512 threads / 16 warps.
// X tile [64][516] fp32 resident in SMEM across both 512x512 layers.
// W streamed as [16][520] k-major chunks via cp.async, double-buffered.
// Warp tile: 32 rows x 64 cols (2 row-tiles x 8 col-tiles of m16n8k8).
#define LDX 516
#define WROW 520
#define X_BYTES (64 * LDX * 4)          // 132096
#define WC_BYTES (16 * WROW * 4)        // 33280
#define SMEM_FFN (X_BYTES + 2 * WC_BYTES)  // 198656

__global__ void __launch_bounds__(512, 1) k_ffn_tc(
    const float* __restrict__ hg, const float* __restrict__ hm,
    const float* __restrict__ b1,
    const float* __restrict__ W2r, const float* __restrict__ b2,
    const float* __restrict__ W3r, const float* __restrict__ b3,
    float* __restrict__ pool)
{
    extern __shared__ unsigned char smem[];
    float* Xs = (float*)smem;
    float* Wc0 = (float*)(smem + X_BYTES);
    float* Wc1 = (float*)(smem + X_BYTES + WC_BYTES);
    const uint32_t sb = smem_u32(smem);
    const uint32_t wc_base = sb + X_BYTES;

    const int tid = threadIdx.x;
    const int lane = tid & 31;
    const int wid = tid >> 5;
    const int g = lane >> 2;
    const int t = lane & 3;
    const int rowbase = (wid >> 3) * 32;   // 0 or 32
    const int colbase = (wid & 7) * 64;    // 0..448
    const int b = blockIdx.y;
    const int g0 = blockIdx.x * 64;
    const int valid = min(64, NG - g0);

    // ---- fill X = round_tf32(relu(hg + hm + b1)) ----
    for (int i = tid; i < 64 * 128; i += 512) {
        int r = i >> 7, q = (i & 127) * 4;
        float4 v = make_float4(0.f, 0.f, 0.f, 0.f);
        if (r < valid) {
            float4 a = *(const float4*)(hg + (size_t)(g0 + r) * H2 + q);
            float4 m = *(const float4*)(hm + (size_t)b * H2 + q);
            float4 c = *(const float4*)(b1 + q);
            v.x = cvt_tf32(fmaxf(a.x + m.x + c.x, 0.f));
            v.y = cvt_tf32(fmaxf(a.y + m.y + c.y, 0.f));
            v.z = cvt_tf32(fmaxf(a.z + m.z + c.z, 0.f));
            v.w = cvt_tf32(fmaxf(a.w + m.w + c.w, 0.f));
        }
        *(float4*)(Xs + r * LDX + q) = v;
    }
    __syncthreads();

    float acc[2][8][4];

    for (int layer = 0; layer < 2; ++layer) {
        const float* W = layer ? W3r : W2r;
        const float* bias = layer ? b3 : b2;
#pragma unroll
        for (int rt = 0; rt < 2; ++rt)
#pragma unroll
            for (int ct = 0; ct < 8; ++ct)
#pragma unroll
                for (int j = 0; j < 4; ++j) acc[rt][ct][j] = 0.f;

        // prologue: prefetch chunks 0,1
#pragma unroll
        for (int pc = 0; pc < 2; ++pc) {
            for (int i = tid; i < 2048; i += 512) {
                int kk = i >> 7, q = (i & 127) * 4;
                cp_async16(wc_base + pc * WC_BYTES + (uint32_t)(kk * WROW + q) * 4,
                           W + (size_t)(pc * 16 + kk) * H2 + q);
            }
            cp_commit();
        }

        for (int kb = 0; kb < 32; ++kb) {
            cp_wait<1>();
            __syncthreads();
            const int buf = kb & 1;
            const float* Wc = buf ? Wc1 : Wc0;
            const int kabs = kb * 16;
#pragma unroll
            for (int ks = 0; ks < 2; ++ks) {
                const int kk = ks * 8;
                uint32_t a[2][4];
#pragma unroll
                for (int rt = 0; rt < 2; ++rt) {
                    const float* xp = Xs + (size_t)(rowbase + rt * 16 + g) * LDX + kabs + kk + t;
                    a[rt][0] = __float_as_uint(xp[0]);
                    a[rt][1] = __float_as_uint(xp[8 * LDX]);
                    a[rt][2] = __float_as_uint(xp[4]);
                    a[rt][3] = __float_as_uint(xp[8 * LDX + 4]);
                }
#pragma unroll
                for (int ct = 0; ct < 8; ++ct) {
                    int col = colbase + ct * 8 + g;
                    uint32_t b0 = __float_as_uint(Wc[(kk + t) * WROW + col]);
                    uint32_t bq = __float_as_uint(Wc[(kk + t + 4) * WROW + col]);
                    mma_tf32(acc[0][ct], a[0], b0, bq);
                    mma_tf32(acc[1][ct], a[1], b0, bq);
                }
            }
            __syncthreads();
            if (kb + 2 < 32) {
                for (int i = tid; i < 2048; i += 512) {
                    int kk = i >> 7, q = (i & 127) * 4;
                    cp_async16(wc_base + buf * WC_BYTES + (uint32_t)(kk * WROW + q) * 4,
                               W + (size_t)((kb + 2) * 16 + kk) * H2 + q);
                }
            }
            cp_commit();
        }
        cp_wait<0>();
        __syncthreads();

        if (layer == 0) {
            // X <- round_tf32(relu(acc + b2))
#pragma unroll
            for (int rt = 0; rt < 2; ++rt) {
                int r0 = rowbase + rt * 16 + g;
#pragma unroll
                for (int ct = 0; ct < 8; ++ct) {
                    int col = colbase + ct * 8 + t * 2;
                    float ba = bias[col], bb = bias[col + 1];
                    Xs[r0 * LDX + col]           = cvt_tf32(fmaxf(acc[rt][ct][0] + ba, 0.f));
                    Xs[r0 * LDX + col + 1]       = cvt_tf32(fmaxf(acc[rt][ct][1] + bb, 0.f));
                    Xs[(r0 + 8) * LDX + col]     = cvt_tf32(fmaxf(acc[rt][ct][2] + ba, 0.f));
                    Xs[(r0 + 8) * LDX + col + 1] = cvt_tf32(fmaxf(acc[rt][ct][3] + bb, 0.f));
                }
            }
            __syncthreads();
        } else {
            // gene-sum of relu(acc + b3) over valid rows -> pool[b]
            float* red = Wc0;  // reuse (cp.async drained)
            if (tid < 512) red[tid] = 0.f;
            __syncthreads();
#pragma unroll
            for (int ct = 0; ct < 8; ++ct) {
                int col = colbase + ct * 8 + t * 2;
#pragma unroll
                for (int j = 0; j < 2; ++j) {
                    float bv = bias[col + j];
                    float s = 0.f;
#pragma unroll
                    for (int rt = 0; rt < 2; ++rt) {
                        int r0 = rowbase + rt * 16 + g;
                        if (r0 < valid)     s += fmaxf(acc[rt][ct][j] + bv, 0.f);
                        if (r0 + 8 < valid) s += fmaxf(acc[rt][ct][2 + j] + bv, 0.f);
                    }
                    s += __shfl_xor_sync(0xFFFFFFFFu, s, 4);
                    s += __shfl_xor_sync(0xFFFFFFFFu, s, 8);
                    s += __shfl_xor_sync(0xFFFFFFFFu, s, 16);
                    if (g == 0) atomicAdd(&red[col + j], s);
                }
            }
            __syncthreads();
            if (tid < 512) atomicAdd(&pool[(size_t)b * H2 + tid], red[tid]);
        }
    }
}

// ---------------- launch ----------------
extern "C" void kernel_launch(void* const* d_in, const int* in_sizes, int n_in,
                              void* d_out, int out_size) {
    const float* mol  = (const float*)d_in[0];
    const float* gene = (const float*)d_in[1];
    const int*   ei   = (const int*)d_in[2];
    const float* g1w  = (const float*)d_in[3];
    const float* g1b  = (const float*)d_in[4];
    const float* g2w  = (const float*)d_in[5];
    const float* g2b  = (const float*)d_in[6];
    const float* f1w  = (const float*)d_in[7];
    const float* f1b  = (const float*)d_in[8];
    const float* f2w  = (const float*)d_in[9];
    const float* f2b  = (const float*)d_in[10];
    const float* f3w  = (const float*)d_in[11];
    const float* f3b  = (const float*)d_in[12];
    const float* f4w  = (const float*)d_in[13];
    const float* f4b  = (const float*)d_in[14];
    float* out = (float*)d_out;

    int E = in_sizes[2] / 2;
    const int* src = ei;
    const int* dst = ei + E;

    float *bufA, *bufB, *hg, *hm, *pool, *w2r, *w3r;
    cudaGetSymbolAddress((void**)&bufA, d_bufA);
    cudaGetSymbolAddress((void**)&bufB, d_bufB);
    cudaGetSymbolAddress((void**)&hg, d_hg);
    cudaGetSymbolAddress((void**)&hm, d_hm);
    cudaGetSymbolAddress((void**)&pool, d_pool);
    cudaGetSymbolAddress((void**)&w2r, d_w2r);
    cudaGetSymbolAddress((void**)&w3r, d_w3r);

    // degree + normalization
    k_deg_init<<<(NG + 255) / 256, 256>>>();
    k_deg_count<<<(E + 255) / 256, 256>>>(dst, E);
    k_dinv<<<(NG + 255) / 256, 256>>>();

    // tf32-round FFN weights (layout unchanged [k][n])
    k_round_tf32<<<1024, 256>>>(f2w, w2r, H2 * H2);
    k_round_tf32<<<1024, 256>>>(f3w, w3r, H2 * H2);

    // GCN layer 1
    sgemm<<<dim3((HD + 63) / 64, (NG + 63) / 64), 256>>>(
        gene, HD, g1w, HD, bufA, HD, NG, HD, HD, nullptr, 1.0f);
    k_scatter_init<<<(NG * HD + 255) / 256, 256>>>(bufA, bufB, g1b);
    k_scatter_edges<<<(E * HD + 255) / 256, 256>>>(bufA, bufB, src, dst, E);

    // GCN layer 2
    sgemm<<<dim3((HD + 63) / 64, (NG + 63) / 64), 256>>>(
        bufB, HD, g2w, HD, bufA, HD, NG, HD, HD, nullptr, 1.0f);
    k_scatter_init<<<(NG * HD + 255) / 256, 256>>>(bufA, bufB, g2b);
    k_scatter_edges<<<(E * HD + 255) / 256, 256>>>(bufA, bufB, src, dst, E);

    // ffn1 split: hg = g2 @ W1[:300], hm = mol @ W1[300:]
    sgemm<<<dim3(8, (NG + 63) / 64), 256>>>(
        bufB, HD, f1w, H2, hg, H2, NG, H2, HD, nullptr, 1.0f);
    sgemm<<<dim3(8, 2), 256>>>(
        mol, HD, f1w + HD * H2, H2, hm, H2, NB, H2, HD, nullptr, 1.0f);

    // pool accumulator
    k_zero<<<(NB * H2 + 255) / 256, 256>>>(pool, NB * H2);

    // fused ffn2+ffn3+mean-partial on tensor cores
    cudaFuncSetAttribute(k_ffn_tc, cudaFuncAttributeMaxDynamicSharedMemorySize, SMEM_FFN);
    k_ffn_tc<<<dim3(16, NB), 512, SMEM_FFN>>>(hg, hm, f1b, w2r, f2b, w3r, f3b, pool);

    // out = (pool/978) @ ffn4_w + ffn4_b
    sgemm<<<dim3((NG + 63) / 64, 2), 256>>>(
        pool, H2, f4w, NG, out, NG, NB, NG, H2, f4b, 1.0f / 978.0f);
}